// round 8
// baseline (speedup 1.0000x reference)
#include <cuda_runtime.h>
#include <cuda_fp16.h>
#include <cuda_bf16.h>
#include <mma.h>
#include <cstdint>

using namespace nvcuda;

#define Bn 2
#define Cn 31
#define Dn 7
#define Hn 192
#define Wn 192
#define HWn (Hn * Wn)          // 36864
#define KP 70                  // KAN_PARAMS
#define COEF_LEN 56
#define NB 8                   // N_BASIS

// ---------------- scratch (no allocations allowed) ----------------
__device__ float g_ctx[Bn * Cn * HWn];   // [B, C, H, W]   ~9.1 MB
__device__ float g_wts[Bn * KP * HWn];   // [B, 70, H, W]  ~20.6 MB

// ---------------- kernel 1: mean over D (float4, round-3 form) ----------------
__global__ void mean_kernel(const float* __restrict__ x) {
    int i = blockIdx.x * 256 + threadIdx.x;        // float4 index
    const int HW4 = HWn / 4;                       // 9216
    int hw4 = i % HW4;
    int bc  = i / HW4;
    const float4* p = (const float4*)(x + (size_t)bc * Dn * HWn) + hw4;
    float4 s = make_float4(0.f, 0.f, 0.f, 0.f);
#pragma unroll
    for (int d = 0; d < Dn; d++) {
        float4 v = p[(size_t)d * HW4];
        s.x += v.x; s.y += v.y; s.z += v.z; s.w += v.w;
    }
    const float inv7 = 1.0f / 7.0f;
    s.x *= inv7; s.y *= inv7; s.z *= inv7; s.w *= inv7;
    ((float4*)g_ctx)[i] = s;
}

// ---------------- kernel 2: 3x3 conv 31->70 via wmma fp16 (HMMA) ----------------
// One CTA = 128 row-major pixels, 256 threads (8 warps).
// D[128, 80] = A[128, K=320] * B[320, 80];  k = ci*10 + kk (kk<9 real), co padded 70->80.
// Warp w computes M-tile w (16 px) x 5 N-tiles (80 co), 20 K-steps of 16.
#define KPAD 320
#define NPAD 80
#define LDA  328                           // halves; 656 B/row (16B multiple)
#define A_HALVES (128 * LDA)               // 41,984 -> 83,968 B
#define SM_B_OFF (A_HALVES * 2)            // byte offset of B
#define B_HALVES (KPAD * NPAD)             // 25,600 -> 51,200 B
#define CONV_SMEM (SM_B_OFF + B_HALVES * 2)   // 135,168 B

__global__ void __launch_bounds__(256, 1)
conv_wmma_kernel(const float* __restrict__ gw, const float* __restrict__ gb) {
    extern __shared__ char sm[];
    __half* A = (__half*)sm;                         // [128][LDA]
    __half* Bm = (__half*)(sm + SM_B_OFF);           // [320][80]
    float*  C = (float*)sm;                          // [128][80], reuses A after sync

    int tid = threadIdx.x;
    int wid = tid >> 5;
    int tile = blockIdx.x, b = blockIdx.y;

    // ---- zero A (covers k-slot padding + tail cols) ----
    {
        uint32_t* a32 = (uint32_t*)A;
#pragma unroll 1
        for (int i = tid; i < A_HALVES / 2; i += 256) a32[i] = 0u;
    }

    // ---- stage B [k][n]: w(co=n, ci, kk) ----
#pragma unroll 1
    for (int idx = tid; idx < KPAD * NPAD; idx += 256) {
        int k = idx / NPAD;
        int n = idx - k * NPAD;
        int ci = k / 10;
        int kk = k - ci * 10;
        float w = 0.f;
        if (n < 70 && ci < Cn && kk < 9)
            w = gw[((size_t)n * Cn + ci) * 9 + kk];
        Bm[idx] = __float2half(w);
    }

    // ---- stage A: im2col fp16; thread pair (even/odd) shares a pixel ----
    {
        int p   = tid >> 1;
        int pix = tile * 128 + p;
        int y = pix / Wn, x = pix - y * Wn;
        const float* ctx = g_ctx + (size_t)b * Cn * HWn;
        __half* arow = A + (size_t)p * LDA;
#pragma unroll 1
        for (int ci = (tid & 1); ci < Cn; ci += 2) {
            const float* cc = ctx + (size_t)ci * HWn;
            float v[9];
#pragma unroll
            for (int kk = 0; kk < 9; kk++) {
                int dy = kk / 3 - 1, dx = kk % 3 - 1;
                int yy = y + dy, xx = x + dx;
                v[kk] = (yy >= 0 && yy < Hn && xx >= 0 && xx < Wn)
                        ? cc[yy * Wn + xx] : 0.f;
            }
            int k0 = ci * 10;
#pragma unroll
            for (int q = 0; q < 4; q++)
                *(__half2*)(arow + k0 + 2 * q) =
                    __halves2half2(__float2half(v[2 * q]), __float2half(v[2 * q + 1]));
            *(__half2*)(arow + k0 + 8) =
                __halves2half2(__float2half(v[8]), __float2half(0.f));
        }
    }
    __syncthreads();

    // ---- wmma mainloop ----
    wmma::fragment<wmma::accumulator, 16, 16, 16, float> acc[5];
#pragma unroll
    for (int nt = 0; nt < 5; nt++) wmma::fill_fragment(acc[nt], 0.f);

    int m0 = wid * 16;
#pragma unroll 1
    for (int ks = 0; ks < 20; ks++) {
        wmma::fragment<wmma::matrix_a, 16, 16, 16, __half, wmma::row_major> af;
        wmma::load_matrix_sync(af, A + (size_t)m0 * LDA + ks * 16, LDA);
#pragma unroll
        for (int nt = 0; nt < 5; nt++) {
            wmma::fragment<wmma::matrix_b, 16, 16, 16, __half, wmma::row_major> bf;
            wmma::load_matrix_sync(bf, Bm + (size_t)(ks * 16) * NPAD + nt * 16, NPAD);
            wmma::mma_sync(acc[nt], af, bf, acc[nt]);
        }
    }

    __syncthreads();   // everyone done reading A/B before C overwrites
#pragma unroll
    for (int nt = 0; nt < 5; nt++)
        wmma::store_matrix_sync(C + (size_t)m0 * NPAD + nt * 16, acc[nt], NPAD, wmma::mem_row_major);
    __syncthreads();

    // ---- write out: coalesced over pixels per co ----
    float* outp = g_wts + (size_t)b * KP * HWn + tile * 128;
#pragma unroll 1
    for (int idx = tid; idx < 70 * 128; idx += 256) {
        int co = idx >> 7;
        int p  = idx & 127;
        outp[(size_t)co * HWn + p] = C[(size_t)p * NPAD + co] + __ldg(gb + co);
    }
}

// ---------------- kernel 3: fused bspline + silu (round-6 logic, 128-thr blocks) ----------------
// 128 threads/block -> smem 50,688 B -> 4 blocks/SM = 16 warps (was 8).
#define KAN_ROW 99
#define KAN_SMEM_BYTES (128 * KAN_ROW * 4)

__global__ void __launch_bounds__(128, 4)
kan_kernel(const float* __restrict__ xin, float* __restrict__ out) {
    extern __shared__ float smem[];
    int tid = threadIdx.x;
    int b = blockIdx.y;
    int p = blockIdx.x * 128 + tid;

    float* ws = smem + tid * KAN_ROW;
    const float* wbase = g_wts + (size_t)b * KP * HWn + p;

#pragma unroll
    for (int d = 0; d < Dn; d++) {
        ws[d * 14 + 0]  = 0.f; ws[d * 14 + 1]  = 0.f; ws[d * 14 + 2]  = 0.f;
        ws[d * 14 + 11] = 0.f; ws[d * 14 + 12] = 0.f; ws[d * 14 + 13] = 0.f;
    }
#pragma unroll
    for (int k = 0; k < COEF_LEN; k++) {
        int d = k >> 3, g = k & 7;
        ws[d * 14 + 3 + g] = wbase[(size_t)k * HWn];
    }

    float uw[Dn], rw[Dn];
#pragma unroll
    for (int d = 0; d < Dn; d++) {
        uw[d] = wbase[(size_t)(COEF_LEN + d) * HWn] * (1.0f / 6.0f);
        rw[d] = wbase[(size_t)(COEF_LEN + Dn + d) * HWn];
    }

    const float* xb = xin + (size_t)b * Cn * Dn * HWn + p;
    float* ob = out + (size_t)b * Cn * HWn + p;

#pragma unroll 1
    for (int c0 = 0; c0 < Cn; c0 += 4) {
        float xv[4][Dn];
#pragma unroll
        for (int cc = 0; cc < 4; cc++) {
            if (c0 + cc < Cn) {
#pragma unroll
                for (int d = 0; d < Dn; d++)
                    xv[cc][d] = xb[(size_t)((c0 + cc) * Dn + d) * HWn];
            }
        }
#pragma unroll
        for (int cc = 0; cc < 4; cc++) {
            if (c0 + cc < Cn) {
                float acc = 0.f;
#pragma unroll
                for (int d = 0; d < Dn; d++) {
                    float x = xv[cc][d];
                    float xs = fmaf(x, 2.5f, 5.5f);
                    float jf = floorf(xs);
                    int j = (int)jf;
                    float t = xs - jf;
                    unsigned ju = (unsigned)j;
                    float vm = (ju <= 10u) ? 1.f : 0.f;
                    int jc = (ju <= 10u) ? j : 0;

                    float t2 = t * t;
                    float t3 = t2 * t;
                    float omt = 1.f - t;
                    float u0 = omt * omt * omt;
                    float u1 = 3.f * t3 - 6.f * t2 + 4.f;
                    float u2 = -3.f * t3 + 3.f * t2 + 3.f * t + 1.f;
                    float u3 = t3;

                    const float* cf = ws + d * 14 + jc;
                    float sa = u0 * cf[0];
                    sa = fmaf(u1, cf[1], sa);
                    sa = fmaf(u2, cf[2], sa);
                    sa = fmaf(u3, cf[3], sa);
                    acc = fmaf(sa * vm, uw[d], acc);

                    float sig = 1.f / (1.f + __expf(-x));
                    acc = fmaf(x * sig, rw[d], acc);
                }
                ob[(size_t)(c0 + cc) * HWn] = acc;
            }
        }
    }
}

// ---------------- launch ----------------
extern "C" void kernel_launch(void* const* d_in, const int* in_sizes, int n_in,
                              void* d_out, int out_size) {
    const float* x  = (const float*)d_in[0];   // windowed_x [2,31,7,192,192]
    const float* gw = (const float*)d_in[1];   // gen_w [70,31,3,3]
    const float* gb = (const float*)d_in[2];   // gen_b [70]
    float* out = (float*)d_out;                // [2,31,192,192]

    cudaFuncSetAttribute(conv_wmma_kernel, cudaFuncAttributeMaxDynamicSharedMemorySize, CONV_SMEM);
    cudaFuncSetAttribute(kan_kernel,       cudaFuncAttributeMaxDynamicSharedMemorySize, KAN_SMEM_BYTES);

    mean_kernel<<<(Bn * Cn * HWn / 4) / 256, 256>>>(x);
    conv_wmma_kernel<<<dim3(HWn / 128, Bn), 256, CONV_SMEM>>>(gw, gb);
    kan_kernel<<<dim3(HWn / 128, Bn), 128, KAN_SMEM_BYTES>>>(x, out);
}

// round 9
// speedup vs baseline: 1.1935x; 1.1935x over previous
#include <cuda_runtime.h>
#include <cuda_bf16.h>
#include <cstdint>

#define Bn 2
#define Cn 31
#define Dn 7
#define Hn 192
#define Wn 192
#define HWn (Hn * Wn)          // 36864
#define KP 70                  // KAN_PARAMS
#define COEF_LEN 56
#define NB 8                   // N_BASIS

// ---------------- scratch (no allocations allowed) ----------------
__device__ float g_ctx[Bn * Cn * HWn];   // [B, C, H, W]   ~9.1 MB
__device__ float g_wts[Bn * KP * HWn];   // [B, 70, H, W]  ~20.6 MB

// ---------------- packed f32x2 helpers (sm_103a FFMA2) ----------------
__device__ __forceinline__ unsigned long long fma2(unsigned long long a,
                                                   unsigned long long b,
                                                   unsigned long long c) {
    unsigned long long d;
    asm("fma.rn.f32x2 %0, %1, %2, %3;" : "=l"(d) : "l"(a), "l"(b), "l"(c));
    return d;
}
__device__ __forceinline__ unsigned long long pack2(float lo, float hi) {
    unsigned long long d;
    asm("mov.b64 %0, {%1, %2};" : "=l"(d) : "f"(lo), "f"(hi));
    return d;
}
__device__ __forceinline__ void unpack2(unsigned long long v, float& lo, float& hi) {
    asm("mov.b64 {%0, %1}, %2;" : "=f"(lo), "=f"(hi) : "l"(v));
}

// ---------------- kernel 1: mean over D (float4, round-3 form) ----------------
__global__ void mean_kernel(const float* __restrict__ x) {
    int i = blockIdx.x * 256 + threadIdx.x;        // float4 index
    const int HW4 = HWn / 4;                       // 9216
    int hw4 = i % HW4;
    int bc  = i / HW4;
    const float4* p = (const float4*)(x + (size_t)bc * Dn * HWn) + hw4;
    float4 s = make_float4(0.f, 0.f, 0.f, 0.f);
#pragma unroll
    for (int d = 0; d < Dn; d++) {
        float4 v = p[(size_t)d * HW4];
        s.x += v.x; s.y += v.y; s.z += v.z; s.w += v.w;
    }
    const float inv7 = 1.0f / 7.0f;
    s.x *= inv7; s.y *= inv7; s.z *= inv7; s.w *= inv7;
    ((float4*)g_ctx)[i] = s;
}

// ---------------- kernel 2: 3x3 SAME conv 31->70 + bias (f32x2, round-6 form) ----------------
#define TILE_W 64
#define TILE_H 16
#define TC 10
#define CI_CHUNK 16
#define S_TILE_FLOATS (CI_CHUNK * 18 * 66)          // 19008 floats = 76032 B
#define S_W_PAIRS     (Cn * 9 * TC)                 // 2790 pairs   = 22320 B
#define CONV_SMEM_BYTES (S_TILE_FLOATS * 4 + S_W_PAIRS * 8)

__global__ void __launch_bounds__(256, 2)
conv_kernel(const float* __restrict__ gw, const float* __restrict__ gb) {
    extern __shared__ char smem_raw[];
    float* s_tile = (float*)smem_raw;                                    // [ci_chunk][18][66]
    unsigned long long* s_wd = (unsigned long long*)(smem_raw + S_TILE_FLOATS * 4);

    int tid = threadIdx.x;
    int bz = blockIdx.z;
    int cochunk = bz % 7;
    int b = bz / 7;

    int ox = blockIdx.x * TILE_W - 1;
    int oy = blockIdx.y * TILE_H - 1;
    const float* ctx = g_ctx + (size_t)b * Cn * HWn;

    // stage duplicated weight pairs for this cout chunk (once)
    for (int idx = tid; idx < S_W_PAIRS; idx += 256) {
        int j = idx % TC;
        int r = idx / TC;                 // ci*9 + kk
        int ci = r / 9, kk = r % 9;
        int co = cochunk * TC + j;
        float w = gw[((size_t)co * Cn + ci) * 9 + kk];
        s_wd[idx] = pack2(w, w);
    }

    int lx = (tid & 31) * 2;              // 0..62
    int ly = (tid >> 5) * 2;              // 0..14

    unsigned long long acc[2][TC];
#pragma unroll
    for (int p = 0; p < 2; p++)
#pragma unroll
        for (int j = 0; j < TC; j++) acc[p][j] = 0ull;

    for (int c0 = 0; c0 < Cn; c0 += CI_CHUNK) {
        int nc = (Cn - c0 < CI_CHUNK) ? (Cn - c0) : CI_CHUNK;
        // stage input tile chunk (with halo, zero-padded)
        for (int idx = tid; idx < nc * 18 * 66; idx += 256) {
            int ci = idx / (18 * 66);
            int r  = idx % (18 * 66);
            int y = r / 66, xx = r % 66;
            int gy = oy + y, gx = ox + xx;
            float v = 0.f;
            if (gy >= 0 && gy < Hn && gx >= 0 && gx < Wn)
                v = ctx[(size_t)(c0 + ci) * HWn + gy * Wn + gx];
            s_tile[idx] = v;
        }
        __syncthreads();

#pragma unroll 1
        for (int cl = 0; cl < nc; cl++) {
            const float* t = s_tile + cl * (18 * 66);
            int ci_g = c0 + cl;

#pragma unroll
            for (int ky = 0; ky < 3; ky++) {
                float2 a0 = *(const float2*)(t + (ly + ky) * 66 + lx);
                float2 a1 = *(const float2*)(t + (ly + ky) * 66 + lx + 2);
                float2 b0 = *(const float2*)(t + (ly + ky + 1) * 66 + lx);
                float2 b1 = *(const float2*)(t + (ly + ky + 1) * 66 + lx + 2);
                unsigned long long pa[3], pb[3];
                pa[0] = pack2(a0.x, a0.y); pa[1] = pack2(a0.y, a1.x); pa[2] = pack2(a1.x, a1.y);
                pb[0] = pack2(b0.x, b0.y); pb[1] = pack2(b0.y, b1.x); pb[2] = pack2(b1.x, b1.y);

#pragma unroll
                for (int kx = 0; kx < 3; kx++) {
                    const ulonglong2* wrow =
                        (const ulonglong2*)(s_wd + (size_t)(ci_g * 9 + ky * 3 + kx) * TC);
                    ulonglong2 w01 = wrow[0];
                    ulonglong2 w23 = wrow[1];
                    ulonglong2 w45 = wrow[2];
                    ulonglong2 w67 = wrow[3];
                    ulonglong2 w89 = wrow[4];
                    unsigned long long wv[TC] = {w01.x, w01.y, w23.x, w23.y, w45.x,
                                                 w45.y, w67.x, w67.y, w89.x, w89.y};
#pragma unroll
                    for (int j = 0; j < TC; j++) {
                        acc[0][j] = fma2(pa[kx], wv[j], acc[0][j]);
                        acc[1][j] = fma2(pb[kx], wv[j], acc[1][j]);
                    }
                }
            }
        }
        __syncthreads();
    }

    int gx = blockIdx.x * TILE_W + lx;
    float* outp = g_wts + (size_t)b * KP * HWn;
#pragma unroll
    for (int j = 0; j < TC; j++) {
        int co = cochunk * TC + j;
        float bias = __ldg(gb + co);
#pragma unroll
        for (int p = 0; p < 2; p++) {
            int gy = blockIdx.y * TILE_H + ly + p;
            float lo, hi;
            unpack2(acc[p][j], lo, hi);
            *(float2*)(outp + (size_t)co * HWn + gy * Wn + gx) =
                make_float2(lo + bias, hi + bias);
        }
    }
}

// ---------------- kernel 3: fused bspline + silu (128-thr blocks, 4/SM) ----------------
// ONLY delta vs the 163.9 baseline: 128 threads/block -> smem 50,688 B ->
// 4 blocks/SM = 16 warps resident (was 8). Kernel logic identical.
#define KAN_ROW 99
#define KAN_SMEM_BYTES (128 * KAN_ROW * 4)

__global__ void __launch_bounds__(128, 4)
kan_kernel(const float* __restrict__ xin, float* __restrict__ out) {
    extern __shared__ float smem[];
    int tid = threadIdx.x;
    int b = blockIdx.y;
    int p = blockIdx.x * 128 + tid;

    float* ws = smem + tid * KAN_ROW;
    const float* wbase = g_wts + (size_t)b * KP * HWn + p;

#pragma unroll
    for (int d = 0; d < Dn; d++) {
        ws[d * 14 + 0]  = 0.f; ws[d * 14 + 1]  = 0.f; ws[d * 14 + 2]  = 0.f;
        ws[d * 14 + 11] = 0.f; ws[d * 14 + 12] = 0.f; ws[d * 14 + 13] = 0.f;
    }
#pragma unroll
    for (int k = 0; k < COEF_LEN; k++) {
        int d = k >> 3, g = k & 7;
        ws[d * 14 + 3 + g] = wbase[(size_t)k * HWn];
    }

    float uw[Dn], rw[Dn];
#pragma unroll
    for (int d = 0; d < Dn; d++) {
        uw[d] = wbase[(size_t)(COEF_LEN + d) * HWn] * (1.0f / 6.0f);
        rw[d] = wbase[(size_t)(COEF_LEN + Dn + d) * HWn];
    }

    const float* xb = xin + (size_t)b * Cn * Dn * HWn + p;
    float* ob = out + (size_t)b * Cn * HWn + p;

#pragma unroll 1
    for (int c0 = 0; c0 < Cn; c0 += 4) {
        float xv[4][Dn];
#pragma unroll
        for (int cc = 0; cc < 4; cc++) {
            if (c0 + cc < Cn) {
#pragma unroll
                for (int d = 0; d < Dn; d++)
                    xv[cc][d] = xb[(size_t)((c0 + cc) * Dn + d) * HWn];
            }
        }
#pragma unroll
        for (int cc = 0; cc < 4; cc++) {
            if (c0 + cc < Cn) {
                float acc = 0.f;
#pragma unroll
                for (int d = 0; d < Dn; d++) {
                    float x = xv[cc][d];
                    float xs = fmaf(x, 2.5f, 5.5f);
                    float jf = floorf(xs);
                    int j = (int)jf;
                    float t = xs - jf;
                    unsigned ju = (unsigned)j;
                    float vm = (ju <= 10u) ? 1.f : 0.f;
                    int jc = (ju <= 10u) ? j : 0;

                    float t2 = t * t;
                    float t3 = t2 * t;
                    float omt = 1.f - t;
                    float u0 = omt * omt * omt;
                    float u1 = 3.f * t3 - 6.f * t2 + 4.f;
                    float u2 = -3.f * t3 + 3.f * t2 + 3.f * t + 1.f;
                    float u3 = t3;

                    const float* cf = ws + d * 14 + jc;
                    float sa = u0 * cf[0];
                    sa = fmaf(u1, cf[1], sa);
                    sa = fmaf(u2, cf[2], sa);
                    sa = fmaf(u3, cf[3], sa);
                    acc = fmaf(sa * vm, uw[d], acc);

                    float sig = 1.f / (1.f + __expf(-x));
                    acc = fmaf(x * sig, rw[d], acc);
                }
                ob[(size_t)(c0 + cc) * HWn] = acc;
            }
        }
    }
}

// ---------------- launch ----------------
extern "C" void kernel_launch(void* const* d_in, const int* in_sizes, int n_in,
                              void* d_out, int out_size) {
    const float* x  = (const float*)d_in[0];   // windowed_x [2,31,7,192,192]
    const float* gw = (const float*)d_in[1];   // gen_w [70,31,3,3]
    const float* gb = (const float*)d_in[2];   // gen_b [70]
    float* out = (float*)d_out;                // [2,31,192,192]

    cudaFuncSetAttribute(conv_kernel, cudaFuncAttributeMaxDynamicSharedMemorySize, CONV_SMEM_BYTES);
    cudaFuncSetAttribute(kan_kernel,  cudaFuncAttributeMaxDynamicSharedMemorySize, KAN_SMEM_BYTES);

    mean_kernel<<<(Bn * Cn * HWn / 4) / 256, 256>>>(x);
    conv_kernel<<<dim3(Wn / TILE_W, Hn / TILE_H, Bn * 7), 256, CONV_SMEM_BYTES>>>(gw, gb);
    kan_kernel<<<dim3(HWn / 128, Bn), 128, KAN_SMEM_BYTES>>>(x, out);
}

// round 10
// speedup vs baseline: 2.2507x; 1.8858x over previous
#include <cuda_runtime.h>
#include <cuda_fp16.h>
#include <cuda_bf16.h>
#include <mma.h>
#include <cstdint>

using namespace nvcuda;

#define Bn 2
#define Cn 31
#define Dn 7
#define Hn 192
#define Wn 192
#define HWn (Hn * Wn)          // 36864
#define KP 70                  // KAN_PARAMS
#define COEF_LEN 56
#define NB 8                   // N_BASIS

// ---------------- scratch (no allocations allowed) ----------------
__device__ float  g_ctx[Bn * Cn * HWn];   // [B, C, H, W]
__device__ float  g_wts[Bn * KP * HWn];   // [B, 70, H, W]
__device__ __half g_wB[9 * 32 * 80];      // [kk][ci(pad32)][co(pad80)] fp16

// ---------------- kernel 0: one-time weight conversion ----------------
__global__ void wprep_kernel(const float* __restrict__ gw) {
    int idx = blockIdx.x * 256 + threadIdx.x;       // 9*32*80 = 23040
    if (idx >= 9 * 32 * 80) return;
    int kk = idx / 2560;
    int r  = idx - kk * 2560;
    int ci = r / 80;
    int co = r - ci * 80;
    float v = 0.f;
    if (ci < Cn && co < KP) v = gw[((size_t)co * Cn + ci) * 9 + kk];
    g_wB[idx] = __float2half(v);
}

// ---------------- kernel 1: mean over D (float4) ----------------
__global__ void mean_kernel(const float* __restrict__ x) {
    int i = blockIdx.x * 256 + threadIdx.x;        // float4 index
    const int HW4 = HWn / 4;                       // 9216
    int hw4 = i % HW4;
    int bc  = i / HW4;
    const float4* p = (const float4*)(x + (size_t)bc * Dn * HWn) + hw4;
    float4 s = make_float4(0.f, 0.f, 0.f, 0.f);
#pragma unroll
    for (int d = 0; d < Dn; d++) {
        float4 v = p[(size_t)d * HW4];
        s.x += v.x; s.y += v.y; s.z += v.z; s.w += v.w;
    }
    const float inv7 = 1.0f / 7.0f;
    s.x *= inv7; s.y *= inv7; s.z *= inv7; s.w *= inv7;
    ((float4*)g_ctx)[i] = s;
}

// ---------------- kernel 2: conv as 9 shifted GEMMs (wmma fp16, fp32 acc) ----------------
// CTA = 2 image rows = 384 px = 24 M-tiles(16px). 256 thr (8 warps), warp owns 3 M-tiles x 80 co.
// A: ctx tile [4 rows][208 rx][32 ci] fp16, lda=40 (80B rows, 16B-aligned).
// B: g_wB copied to smem (9x32x80). 9 shifts x 2 K-steps of 16.
#define LDA_A 40
#define SA_HALVES (4 * 208 * LDA_A)            // 33,280 -> 66,560 B
#define SB_OFF (SA_HALVES * 2)                 // 66,560
#define SB_HALVES (9 * 32 * 80)                // 23,040 -> 46,080 B
#define SC_OFF (SB_OFF + SB_HALVES * 2)        // 112,640
#define SC_FLOATS (8 * 16 * 84)                // per-warp 16x84 f32 -> 43,008 B
#define CONV_SMEM (SC_OFF + SC_FLOATS * 4)     // 155,648 B

__global__ void __launch_bounds__(256, 1)
conv_wmma_kernel(const float* __restrict__ gb) {
    extern __shared__ char sm[];
    __half* sA = (__half*)sm;
    __half* sB = (__half*)(sm + SB_OFF);
    float*  sC = (float*)(sm + SC_OFF);

    int tid = threadIdx.x;
    int wid = tid >> 5, lane = tid & 31;
    int y0 = blockIdx.x * 2;                      // first of 2 image rows
    int b  = blockIdx.y;

    // ---- stage B: straight u32 copy from pre-converted global ----
    {
        const uint32_t* src = (const uint32_t*)g_wB;
        uint32_t* dst = (uint32_t*)sB;
#pragma unroll
        for (int i = 0; i < SB_HALVES / 2; i += 256)
            dst[i + tid] = src[i + tid];
    }

    // ---- stage A: ctx rows y0-1..y0+2, rx 0..207 (gx = rx-1), 32 ci ----
    {
        const float* ctx = g_ctx + (size_t)b * Cn * HWn;
        int g = tid >> 5;                          // 0..7
#pragma unroll 1
        for (int s = 0; s < 16; s++) {
            int combo = s * 8 + g;                 // 0..127 = (ry, ci)
            int ry = combo >> 5;
            int ci = combo & 31;
            int gy = y0 - 1 + ry;
            bool rowok = (ci < Cn) && (gy >= 0) && (gy < Hn);
            const float* srow = ctx + (size_t)ci * HWn + (size_t)gy * Wn;
            __half* drow = sA + (size_t)(ry * 208) * LDA_A + ci;
#pragma unroll
            for (int rseg = 0; rseg < 7; rseg++) {
                int rx = rseg * 32 + lane;
                if (rx < 208) {
                    int gx = rx - 1;
                    float v = (rowok && gx >= 0 && gx < Wn) ? srow[gx] : 0.f;
                    drow[(size_t)rx * LDA_A] = __float2half(v);
                }
            }
        }
    }
    __syncthreads();

    // ---- mainloop: acc[3 M-tiles][5 N-frags] ----
    wmma::fragment<wmma::accumulator, 16, 16, 16, float> acc[3][5];
#pragma unroll
    for (int mt = 0; mt < 3; mt++)
#pragma unroll
        for (int nt = 0; nt < 5; nt++) wmma::fill_fragment(acc[mt][nt], 0.f);

    int mbase = wid * 3;
#pragma unroll
    for (int kk = 0; kk < 9; kk++) {
        const int dy = kk / 3, dx = kk % 3;
#pragma unroll
        for (int ks = 0; ks < 2; ks++) {
            wmma::fragment<wmma::matrix_b, 16, 16, 16, __half, wmma::row_major> bf[5];
#pragma unroll
            for (int nt = 0; nt < 5; nt++)
                wmma::load_matrix_sync(bf[nt], sB + kk * 2560 + ks * 16 * 80 + nt * 16, 80);
#pragma unroll
            for (int mt = 0; mt < 3; mt++) {
                int m = mbase + mt;                 // 0..23
                int yr = (m >= 12) ? 1 : 0;
                int xt = m - 12 * yr;
                int p0 = (yr + dy) * 208 + xt * 16 + dx;
                wmma::fragment<wmma::matrix_a, 16, 16, 16, __half, wmma::row_major> af;
                wmma::load_matrix_sync(af, sA + (size_t)p0 * LDA_A + ks * 16, LDA_A);
#pragma unroll
                for (int nt = 0; nt < 5; nt++)
                    wmma::mma_sync(acc[mt][nt], af, bf[nt], acc[mt][nt]);
            }
        }
    }

    // ---- epilogue: per-warp C buffer -> coalesced-ish strided stores ----
    float* sCw = sC + (size_t)wid * 16 * 84;
    float* outp = g_wts + (size_t)b * KP * HWn;
#pragma unroll
    for (int mt = 0; mt < 3; mt++) {
        int m = mbase + mt;
        int yr = (m >= 12) ? 1 : 0;
        int xt = m - 12 * yr;
#pragma unroll
        for (int nt = 0; nt < 5; nt++)
            wmma::store_matrix_sync(sCw + nt * 16, acc[mt][nt], 84, wmma::mem_row_major);
        __syncwarp();
        int pix0 = (y0 + yr) * Wn + xt * 16;
        int px = lane & 15;
        int ch = lane >> 4;                        // 0/1
#pragma unroll 1
        for (int i = 0; i < 35; i++) {
            int co = i * 2 + ch;                   // 0..69
            outp[(size_t)co * HWn + pix0 + px] = sCw[(size_t)px * 84 + co] + __ldg(gb + co);
        }
        __syncwarp();
    }
}

// ---------------- kernel 3: fused bspline + silu (round-9 best, unchanged) ----------------
#define KAN_ROW 99
#define KAN_SMEM_BYTES (128 * KAN_ROW * 4)

__global__ void __launch_bounds__(128, 4)
kan_kernel(const float* __restrict__ xin, float* __restrict__ out) {
    extern __shared__ float smem[];
    int tid = threadIdx.x;
    int b = blockIdx.y;
    int p = blockIdx.x * 128 + tid;

    float* ws = smem + tid * KAN_ROW;
    const float* wbase = g_wts + (size_t)b * KP * HWn + p;

#pragma unroll
    for (int d = 0; d < Dn; d++) {
        ws[d * 14 + 0]  = 0.f; ws[d * 14 + 1]  = 0.f; ws[d * 14 + 2]  = 0.f;
        ws[d * 14 + 11] = 0.f; ws[d * 14 + 12] = 0.f; ws[d * 14 + 13] = 0.f;
    }
#pragma unroll
    for (int k = 0; k < COEF_LEN; k++) {
        int d = k >> 3, g = k & 7;
        ws[d * 14 + 3 + g] = wbase[(size_t)k * HWn];
    }

    float uw[Dn], rw[Dn];
#pragma unroll
    for (int d = 0; d < Dn; d++) {
        uw[d] = wbase[(size_t)(COEF_LEN + d) * HWn] * (1.0f / 6.0f);
        rw[d] = wbase[(size_t)(COEF_LEN + Dn + d) * HWn];
    }

    const float* xb = xin + (size_t)b * Cn * Dn * HWn + p;
    float* ob = out + (size_t)b * Cn * HWn + p;

#pragma unroll 1
    for (int c0 = 0; c0 < Cn; c0 += 4) {
        float xv[4][Dn];
#pragma unroll
        for (int cc = 0; cc < 4; cc++) {
            if (c0 + cc < Cn) {
#pragma unroll
                for (int d = 0; d < Dn; d++)
                    xv[cc][d] = xb[(size_t)((c0 + cc) * Dn + d) * HWn];
            }
        }
#pragma unroll
        for (int cc = 0; cc < 4; cc++) {
            if (c0 + cc < Cn) {
                float acc = 0.f;
#pragma unroll
                for (int d = 0; d < Dn; d++) {
                    float x = xv[cc][d];
                    float xs = fmaf(x, 2.5f, 5.5f);
                    float jf = floorf(xs);
                    int j = (int)jf;
                    float t = xs - jf;
                    unsigned ju = (unsigned)j;
                    float vm = (ju <= 10u) ? 1.f : 0.f;
                    int jc = (ju <= 10u) ? j : 0;

                    float t2 = t * t;
                    float t3 = t2 * t;
                    float omt = 1.f - t;
                    float u0 = omt * omt * omt;
                    float u1 = 3.f * t3 - 6.f * t2 + 4.f;
                    float u2 = -3.f * t3 + 3.f * t2 + 3.f * t + 1.f;
                    float u3 = t3;

                    const float* cf = ws + d * 14 + jc;
                    float sa = u0 * cf[0];
                    sa = fmaf(u1, cf[1], sa);
                    sa = fmaf(u2, cf[2], sa);
                    sa = fmaf(u3, cf[3], sa);
                    acc = fmaf(sa * vm, uw[d], acc);

                    float sig = 1.f / (1.f + __expf(-x));
                    acc = fmaf(x * sig, rw[d], acc);
                }
                ob[(size_t)(c0 + cc) * HWn] = acc;
            }
        }
    }
}

// ---------------- launch ----------------
extern "C" void kernel_launch(void* const* d_in, const int* in_sizes, int n_in,
                              void* d_out, int out_size) {
    const float* x  = (const float*)d_in[0];   // windowed_x [2,31,7,192,192]
    const float* gw = (const float*)d_in[1];   // gen_w [70,31,3,3]
    const float* gb = (const float*)d_in[2];   // gen_b [70]
    float* out = (float*)d_out;                // [2,31,192,192]

    cudaFuncSetAttribute(conv_wmma_kernel, cudaFuncAttributeMaxDynamicSharedMemorySize, CONV_SMEM);
    cudaFuncSetAttribute(kan_kernel,       cudaFuncAttributeMaxDynamicSharedMemorySize, KAN_SMEM_BYTES);

    wprep_kernel<<<(9 * 32 * 80 + 255) / 256, 256>>>(gw);
    mean_kernel<<<(Bn * Cn * HWn / 4) / 256, 256>>>(x);
    conv_wmma_kernel<<<dim3(Hn / 2, Bn), 256, CONV_SMEM>>>(gb);
    kan_kernel<<<dim3(HWn / 128, Bn), 128, KAN_SMEM_BYTES>>>(x, out);
}

// round 11
// speedup vs baseline: 2.2709x; 1.0090x over previous
#include <cuda_runtime.h>
#include <cuda_fp16.h>
#include <cuda_bf16.h>
#include <mma.h>
#include <cstdint>

using namespace nvcuda;

#define Bn 2
#define Cn 31
#define Dn 7
#define Hn 192
#define Wn 192
#define HWn (Hn * Wn)          // 36864
#define KP 70                  // KAN_PARAMS
#define COEF_LEN 56
#define NB 8                   // N_BASIS

// ---------------- scratch (no allocations allowed) ----------------
__device__ float  g_ctx[Bn * Cn * HWn];   // [B, C, H, W]
__device__ float  g_wts[Bn * KP * HWn];   // [B, 70, H, W]
__device__ __half g_wB[9 * 32 * 80];      // [kk][ci(pad32)][co(pad80)] fp16

// ---------------- kernel 0: one-time weight conversion ----------------
__global__ void wprep_kernel(const float* __restrict__ gw) {
    int idx = blockIdx.x * 256 + threadIdx.x;       // 9*32*80 = 23040
    if (idx >= 9 * 32 * 80) return;
    int kk = idx / 2560;
    int r  = idx - kk * 2560;
    int ci = r / 80;
    int co = r - ci * 80;
    float v = 0.f;
    if (ci < Cn && co < KP) v = gw[((size_t)co * Cn + ci) * 9 + kk];
    g_wB[idx] = __float2half(v);
}

// ---------------- kernel 1: mean over D (float4) ----------------
__global__ void mean_kernel(const float* __restrict__ x) {
    int i = blockIdx.x * 256 + threadIdx.x;        // float4 index
    const int HW4 = HWn / 4;                       // 9216
    int hw4 = i % HW4;
    int bc  = i / HW4;
    const float4* p = (const float4*)(x + (size_t)bc * Dn * HWn) + hw4;
    float4 s = make_float4(0.f, 0.f, 0.f, 0.f);
#pragma unroll
    for (int d = 0; d < Dn; d++) {
        float4 v = p[(size_t)d * HW4];
        s.x += v.x; s.y += v.y; s.z += v.z; s.w += v.w;
    }
    const float inv7 = 1.0f / 7.0f;
    s.x *= inv7; s.y *= inv7; s.z *= inv7; s.w *= inv7;
    ((float4*)g_ctx)[i] = s;
}

// ---------------- kernel 2: conv as 9 shifted GEMMs (wmma fp16, fp32 acc) ----------------
#define LDA_A 40
#define SA_HALVES (4 * 208 * LDA_A)            // 33,280 -> 66,560 B
#define SB_OFF (SA_HALVES * 2)                 // 66,560
#define SB_HALVES (9 * 32 * 80)                // 23,040 -> 46,080 B
#define SC_OFF (SB_OFF + SB_HALVES * 2)        // 112,640
#define SC_FLOATS (8 * 16 * 84)                // per-warp 16x84 f32 -> 43,008 B
#define CONV_SMEM (SC_OFF + SC_FLOATS * 4)     // 155,648 B

__global__ void __launch_bounds__(256, 1)
conv_wmma_kernel(const float* __restrict__ gb) {
    extern __shared__ char sm[];
    __half* sA = (__half*)sm;
    __half* sB = (__half*)(sm + SB_OFF);
    float*  sC = (float*)(sm + SC_OFF);

    int tid = threadIdx.x;
    int wid = tid >> 5, lane = tid & 31;
    int y0 = blockIdx.x * 2;                      // first of 2 image rows
    int b  = blockIdx.y;

    // ---- stage B: straight u32 copy from pre-converted global ----
    {
        const uint32_t* src = (const uint32_t*)g_wB;
        uint32_t* dst = (uint32_t*)sB;
#pragma unroll
        for (int i = 0; i < SB_HALVES / 2; i += 256)
            dst[i + tid] = src[i + tid];
    }

    // ---- stage A: ctx rows y0-1..y0+2, rx 0..207 (gx = rx-1), 32 ci ----
    {
        const float* ctx = g_ctx + (size_t)b * Cn * HWn;
        int g = tid >> 5;                          // 0..7
#pragma unroll 1
        for (int s = 0; s < 16; s++) {
            int combo = s * 8 + g;                 // 0..127 = (ry, ci)
            int ry = combo >> 5;
            int ci = combo & 31;
            int gy = y0 - 1 + ry;
            bool rowok = (ci < Cn) && (gy >= 0) && (gy < Hn);
            const float* srow = ctx + (size_t)ci * HWn + (size_t)gy * Wn;
            __half* drow = sA + (size_t)(ry * 208) * LDA_A + ci;
#pragma unroll
            for (int rseg = 0; rseg < 7; rseg++) {
                int rx = rseg * 32 + lane;
                if (rx < 208) {
                    int gx = rx - 1;
                    float v = (rowok && gx >= 0 && gx < Wn) ? srow[gx] : 0.f;
                    drow[(size_t)rx * LDA_A] = __float2half(v);
                }
            }
        }
    }
    __syncthreads();

    // ---- mainloop: acc[3 M-tiles][5 N-frags] ----
    wmma::fragment<wmma::accumulator, 16, 16, 16, float> acc[3][5];
#pragma unroll
    for (int mt = 0; mt < 3; mt++)
#pragma unroll
        for (int nt = 0; nt < 5; nt++) wmma::fill_fragment(acc[mt][nt], 0.f);

    int mbase = wid * 3;
#pragma unroll
    for (int kk = 0; kk < 9; kk++) {
        const int dy = kk / 3, dx = kk % 3;
#pragma unroll
        for (int ks = 0; ks < 2; ks++) {
            wmma::fragment<wmma::matrix_b, 16, 16, 16, __half, wmma::row_major> bf[5];
#pragma unroll
            for (int nt = 0; nt < 5; nt++)
                wmma::load_matrix_sync(bf[nt], sB + kk * 2560 + ks * 16 * 80 + nt * 16, 80);
#pragma unroll
            for (int mt = 0; mt < 3; mt++) {
                int m = mbase + mt;                 // 0..23
                int yr = (m >= 12) ? 1 : 0;
                int xt = m - 12 * yr;
                int p0 = (yr + dy) * 208 + xt * 16 + dx;
                wmma::fragment<wmma::matrix_a, 16, 16, 16, __half, wmma::row_major> af;
                wmma::load_matrix_sync(af, sA + (size_t)p0 * LDA_A + ks * 16, LDA_A);
#pragma unroll
                for (int nt = 0; nt < 5; nt++)
                    wmma::mma_sync(acc[mt][nt], af, bf[nt], acc[mt][nt]);
            }
        }
    }

    // ---- epilogue: per-warp C buffer -> strided stores ----
    float* sCw = sC + (size_t)wid * 16 * 84;
    float* outp = g_wts + (size_t)b * KP * HWn;
#pragma unroll
    for (int mt = 0; mt < 3; mt++) {
        int m = mbase + mt;
        int yr = (m >= 12) ? 1 : 0;
        int xt = m - 12 * yr;
#pragma unroll
        for (int nt = 0; nt < 5; nt++)
            wmma::store_matrix_sync(sCw + nt * 16, acc[mt][nt], 84, wmma::mem_row_major);
        __syncwarp();
        int pix0 = (y0 + yr) * Wn + xt * 16;
        int px = lane & 15;
        int ch = lane >> 4;                        // 0/1
#pragma unroll 1
        for (int i = 0; i < 35; i++) {
            int co = i * 2 + ch;                   // 0..69
            outp[(size_t)co * HWn + pix0 + px] = sCw[(size_t)px * 84 + co] + __ldg(gb + co);
        }
        __syncwarp();
    }
}

// ---------------- kernel 3: fused bspline + silu — TRANSPOSED conflict-free table ----------------
// ONLY delta vs 86.0 baseline: table layout [slot][128 px]; every thread owns
// column tid -> bank = tid mod 32 for ANY dynamic slot index -> zero bank
// conflicts on both the fill and the 4-tap gathers. Same smem size (50,176 B),
// same 128-thr/4-block shape, same math.
#define KAN_SLOTS 98                             // 7 d * 14 slots (3 zero-pad each side)
#define KAN_SMEM_BYTES (KAN_SLOTS * 128 * 4)

__global__ void __launch_bounds__(128, 4)
kan_kernel(const float* __restrict__ xin, float* __restrict__ out) {
    extern __shared__ float smem[];
    int tid = threadIdx.x;
    int b = blockIdx.y;
    int p = blockIdx.x * 128 + tid;

    float* col = smem + tid;                      // element (slot s, px tid) at s*128 + tid
    const float* wbase = g_wts + (size_t)b * KP * HWn + p;

    // zero pads
#pragma unroll
    for (int d = 0; d < Dn; d++) {
        col[(d * 14 + 0) * 128]  = 0.f; col[(d * 14 + 1) * 128]  = 0.f; col[(d * 14 + 2) * 128]  = 0.f;
        col[(d * 14 + 11) * 128] = 0.f; col[(d * 14 + 12) * 128] = 0.f; col[(d * 14 + 13) * 128] = 0.f;
    }
    // coefficients (coalesced gmem loads; own column -> no block sync needed)
#pragma unroll
    for (int k = 0; k < COEF_LEN; k++) {
        int d = k >> 3, g = k & 7;
        col[(d * 14 + 3 + g) * 128] = wbase[(size_t)k * HWn];
    }

    float uw[Dn], rw[Dn];
#pragma unroll
    for (int d = 0; d < Dn; d++) {
        uw[d] = wbase[(size_t)(COEF_LEN + d) * HWn] * (1.0f / 6.0f);
        rw[d] = wbase[(size_t)(COEF_LEN + Dn + d) * HWn];
    }

    const float* xb = xin + (size_t)b * Cn * Dn * HWn + p;
    float* ob = out + (size_t)b * Cn * HWn + p;

#pragma unroll 1
    for (int c0 = 0; c0 < Cn; c0 += 4) {
        float xv[4][Dn];
#pragma unroll
        for (int cc = 0; cc < 4; cc++) {
            if (c0 + cc < Cn) {
#pragma unroll
                for (int d = 0; d < Dn; d++)
                    xv[cc][d] = xb[(size_t)((c0 + cc) * Dn + d) * HWn];
            }
        }
#pragma unroll
        for (int cc = 0; cc < 4; cc++) {
            if (c0 + cc < Cn) {
                float acc = 0.f;
#pragma unroll
                for (int d = 0; d < Dn; d++) {
                    float x = xv[cc][d];
                    float xs = fmaf(x, 2.5f, 5.5f);
                    float jf = floorf(xs);
                    int j = (int)jf;
                    float t = xs - jf;
                    unsigned ju = (unsigned)j;
                    float vm = (ju <= 10u) ? 1.f : 0.f;
                    int jc = (ju <= 10u) ? j : 0;

                    float t2 = t * t;
                    float t3 = t2 * t;
                    float omt = 1.f - t;
                    float u0 = omt * omt * omt;
                    float u1 = 3.f * t3 - 6.f * t2 + 4.f;
                    float u2 = -3.f * t3 + 3.f * t2 + 3.f * t + 1.f;
                    float u3 = t3;

                    const float* cf = col + (d * 14 + jc) * 128;   // conflict-free gather
                    float sa = u0 * cf[0];
                    sa = fmaf(u1, cf[128], sa);
                    sa = fmaf(u2, cf[256], sa);
                    sa = fmaf(u3, cf[384], sa);
                    acc = fmaf(sa * vm, uw[d], acc);

                    float sig = 1.f / (1.f + __expf(-x));
                    acc = fmaf(x * sig, rw[d], acc);
                }
                ob[(size_t)(c0 + cc) * HWn] = acc;
            }
        }
    }
}

// ---------------- launch ----------------
extern "C" void kernel_launch(void* const* d_in, const int* in_sizes, int n_in,
                              void* d_out, int out_size) {
    const float* x  = (const float*)d_in[0];   // windowed_x [2,31,7,192,192]
    const float* gw = (const float*)d_in[1];   // gen_w [70,31,3,3]
    const float* gb = (const float*)d_in[2];   // gen_b [70]
    float* out = (float*)d_out;                // [2,31,192,192]

    cudaFuncSetAttribute(conv_wmma_kernel, cudaFuncAttributeMaxDynamicSharedMemorySize, CONV_SMEM);
    cudaFuncSetAttribute(kan_kernel,       cudaFuncAttributeMaxDynamicSharedMemorySize, KAN_SMEM_BYTES);

    wprep_kernel<<<(9 * 32 * 80 + 255) / 256, 256>>>(gw);
    mean_kernel<<<(Bn * Cn * HWn / 4) / 256, 256>>>(x);
    conv_wmma_kernel<<<dim3(Hn / 2, Bn), 256, CONV_SMEM>>>(gb);
    kan_kernel<<<dim3(HWn / 128, Bn), 128, KAN_SMEM_BYTES>>>(x, out);
}

// round 12
// speedup vs baseline: 2.5248x; 1.1118x over previous
#include <cuda_runtime.h>
#include <cuda_fp16.h>
#include <cuda_bf16.h>
#include <mma.h>
#include <cstdint>

using namespace nvcuda;

#define Bn 2
#define Cn 31
#define Dn 7
#define Hn 192
#define Wn 192
#define HWn (Hn * Wn)          // 36864
#define KP 70                  // KAN_PARAMS
#define COEF_LEN 56
#define NB 8                   // N_BASIS

// ---------------- scratch (no allocations allowed) ----------------
__device__ float  g_ctx[Bn * Cn * HWn];   // [B, C, H, W]
__device__ float  g_wts[Bn * KP * HWn];   // [B, 70, H, W]
__device__ __half g_wB[9 * 32 * 80];      // [kk][ci(pad32)][co(pad80)] fp16

// ---------------- kernel 0: one-time weight conversion ----------------
__global__ void wprep_kernel(const float* __restrict__ gw) {
    int idx = blockIdx.x * 256 + threadIdx.x;       // 9*32*80 = 23040
    if (idx >= 9 * 32 * 80) return;
    int kk = idx / 2560;
    int r  = idx - kk * 2560;
    int ci = r / 80;
    int co = r - ci * 80;
    float v = 0.f;
    if (ci < Cn && co < KP) v = gw[((size_t)co * Cn + ci) * 9 + kk];
    g_wB[idx] = __float2half(v);
}

// ---------------- kernel 1: mean over D (float4) ----------------
__global__ void mean_kernel(const float* __restrict__ x) {
    int i = blockIdx.x * 256 + threadIdx.x;        // float4 index
    const int HW4 = HWn / 4;                       // 9216
    int hw4 = i % HW4;
    int bc  = i / HW4;
    const float4* p = (const float4*)(x + (size_t)bc * Dn * HWn) + hw4;
    float4 s = make_float4(0.f, 0.f, 0.f, 0.f);
#pragma unroll
    for (int d = 0; d < Dn; d++) {
        float4 v = p[(size_t)d * HW4];
        s.x += v.x; s.y += v.y; s.z += v.z; s.w += v.w;
    }
    const float inv7 = 1.0f / 7.0f;
    s.x *= inv7; s.y *= inv7; s.z *= inv7; s.w *= inv7;
    ((float4*)g_ctx)[i] = s;
}

// ---------------- kernel 2: conv as 9 shifted GEMMs, single-wave geometry ----------------
// CTA = 3 image rows = 576 px = 36 M-tiles. 384 thr (12 warps), warp = 3 M-tiles x 80 co.
// grid = (64, 2) = 128 CTAs -> ONE wave on 148 SMs.
// A: ctx tile [5 rows][208 rx][32 ci] fp16, lda=40. B: g_wB copy. C overlays A in epilogue.
#define LDA_A 40
#define SA_HALVES (5 * 208 * LDA_A)            // 41,600 -> 83,200 B
#define SB_OFF (SA_HALVES * 2)                 // 83,200
#define SB_HALVES (9 * 32 * 80)                // 23,040 -> 46,080 B
#define CONV_SMEM (SB_OFF + SB_HALVES * 2)     // 129,280 B
// epilogue C overlays sA: 12 warps * 16*84 f32 = 64,512 B <= 83,200 B

__global__ void __launch_bounds__(384, 1)
conv_wmma_kernel(const float* __restrict__ gb) {
    extern __shared__ char sm[];
    __half* sA = (__half*)sm;
    __half* sB = (__half*)(sm + SB_OFF);
    float*  sC = (float*)sm;                      // overlays sA after mainloop

    int tid = threadIdx.x;
    int wid = tid >> 5, lane = tid & 31;
    int y0 = blockIdx.x * 3;                      // first of 3 image rows
    int b  = blockIdx.y;

    // ---- stage B: u32 copy (11520 u32 / 384 thr = 30 exact) ----
    {
        const uint32_t* src = (const uint32_t*)g_wB;
        uint32_t* dst = (uint32_t*)sB;
#pragma unroll
        for (int i = 0; i < SB_HALVES / 2; i += 384)
            dst[i + tid] = src[i + tid];
    }

    // ---- stage A: ctx rows y0-1..y0+3 (5 rows), rx 0..207 (gx = rx-1), 32 ci ----
    {
        const float* ctx = g_ctx + (size_t)b * Cn * HWn;
        int g = tid >> 5;                          // 0..11
#pragma unroll 1
        for (int s = 0; s < 14; s++) {
            int combo = s * 12 + g;                // 0..159 = (ry, ci)
            if (combo < 160) {
                int ry = combo >> 5;               // 0..4
                int ci = combo & 31;
                int gy = y0 - 1 + ry;
                bool rowok = (ci < Cn) && (gy >= 0) && (gy < Hn);
                const float* srow = ctx + (size_t)ci * HWn + (size_t)gy * Wn;
                __half* drow = sA + (size_t)(ry * 208) * LDA_A + ci;
#pragma unroll
                for (int rseg = 0; rseg < 7; rseg++) {
                    int rx = rseg * 32 + lane;
                    if (rx < 208) {
                        int gx = rx - 1;
                        float v = (rowok && gx >= 0 && gx < Wn) ? srow[gx] : 0.f;
                        drow[(size_t)rx * LDA_A] = __float2half(v);
                    }
                }
            }
        }
    }
    __syncthreads();

    // ---- mainloop: acc[3][5]; af[3] preloaded per K-step, bf loaded singly ----
    wmma::fragment<wmma::accumulator, 16, 16, 16, float> acc[3][5];
#pragma unroll
    for (int mt = 0; mt < 3; mt++)
#pragma unroll
        for (int nt = 0; nt < 5; nt++) wmma::fill_fragment(acc[mt][nt], 0.f);

    int mbase = wid * 3;
#pragma unroll
    for (int kk = 0; kk < 9; kk++) {
        const int dy = kk / 3, dx = kk % 3;
#pragma unroll
        for (int ks = 0; ks < 2; ks++) {
            wmma::fragment<wmma::matrix_a, 16, 16, 16, __half, wmma::row_major> af[3];
#pragma unroll
            for (int mt = 0; mt < 3; mt++) {
                int m = mbase + mt;                 // 0..35
                int yr = m / 12;
                int xt = m - 12 * yr;
                int p0 = (yr + dy) * 208 + xt * 16 + dx;
                wmma::load_matrix_sync(af[mt], sA + (size_t)p0 * LDA_A + ks * 16, LDA_A);
            }
#pragma unroll
            for (int nt = 0; nt < 5; nt++) {
                wmma::fragment<wmma::matrix_b, 16, 16, 16, __half, wmma::row_major> bf;
                wmma::load_matrix_sync(bf, sB + kk * 2560 + ks * 16 * 80 + nt * 16, 80);
#pragma unroll
                for (int mt = 0; mt < 3; mt++)
                    wmma::mma_sync(acc[mt][nt], af[mt], bf, acc[mt][nt]);
            }
        }
    }

    __syncthreads();   // all warps done reading sA before sC overlays it

    // ---- epilogue: per-warp C buffer (overlaying sA) -> strided stores ----
    float* sCw = sC + (size_t)wid * 16 * 84;
    float* outp = g_wts + (size_t)b * KP * HWn;
#pragma unroll
    for (int mt = 0; mt < 3; mt++) {
        int m = mbase + mt;
        int yr = m / 12;
        int xt = m - 12 * yr;
#pragma unroll
        for (int nt = 0; nt < 5; nt++)
            wmma::store_matrix_sync(sCw + nt * 16, acc[mt][nt], 84, wmma::mem_row_major);
        __syncwarp();
        int pix0 = (y0 + yr) * Wn + xt * 16;
        int px = lane & 15;
        int ch = lane >> 4;                        // 0/1
#pragma unroll 1
        for (int i = 0; i < 35; i++) {
            int co = i * 2 + ch;                   // 0..69
            outp[(size_t)co * HWn + pix0 + px] = sCw[(size_t)px * 84 + co] + __ldg(gb + co);
        }
        __syncwarp();
    }
}

// ---------------- kernel 3: fused bspline + silu (transposed table, uw premultiplied) ----------------
#define KAN_SLOTS 98                             // 7 d * 14 slots (3 zero-pad each side)
#define KAN_SMEM_BYTES (KAN_SLOTS * 128 * 4)

__global__ void __launch_bounds__(128, 4)
kan_kernel(const float* __restrict__ xin, float* __restrict__ out) {
    extern __shared__ float smem[];
    int tid = threadIdx.x;
    int b = blockIdx.y;
    int p = blockIdx.x * 128 + tid;

    float* col = smem + tid;                      // (slot s, px tid) at s*128 + tid
    const float* wbase = g_wts + (size_t)b * KP * HWn + p;

    float uw[Dn], rw[Dn];
#pragma unroll
    for (int d = 0; d < Dn; d++) {
        uw[d] = wbase[(size_t)(COEF_LEN + d) * HWn] * (1.0f / 6.0f);  // spline 1/6 folded
        rw[d] = wbase[(size_t)(COEF_LEN + Dn + d) * HWn];
    }

    // zero pads
#pragma unroll
    for (int d = 0; d < Dn; d++) {
        col[(d * 14 + 0) * 128]  = 0.f; col[(d * 14 + 1) * 128]  = 0.f; col[(d * 14 + 2) * 128]  = 0.f;
        col[(d * 14 + 11) * 128] = 0.f; col[(d * 14 + 12) * 128] = 0.f; col[(d * 14 + 13) * 128] = 0.f;
    }
    // coefficients premultiplied by uw[d]/6 (coalesced loads; own column, no sync)
#pragma unroll
    for (int k = 0; k < COEF_LEN; k++) {
        int d = k >> 3, g = k & 7;
        col[(d * 14 + 3 + g) * 128] = wbase[(size_t)k * HWn] * uw[d];
    }

    const float* xb = xin + (size_t)b * Cn * Dn * HWn + p;
    float* ob = out + (size_t)b * Cn * HWn + p;

#pragma unroll 1
    for (int c0 = 0; c0 < Cn; c0 += 4) {
        float xv[4][Dn];
#pragma unroll
        for (int cc = 0; cc < 4; cc++) {
            if (c0 + cc < Cn) {
#pragma unroll
                for (int d = 0; d < Dn; d++)
                    xv[cc][d] = xb[(size_t)((c0 + cc) * Dn + d) * HWn];
            }
        }
#pragma unroll
        for (int cc = 0; cc < 4; cc++) {
            if (c0 + cc < Cn) {
                float acc = 0.f;
#pragma unroll
                for (int d = 0; d < Dn; d++) {
                    float x = xv[cc][d];
                    float xs = fmaf(x, 2.5f, 5.5f);
                    float jf = floorf(xs);
                    int j = (int)jf;
                    float t = xs - jf;
                    unsigned ju = (unsigned)j;
                    float vm = (ju <= 10u) ? 1.f : 0.f;
                    int jc = (ju <= 10u) ? j : 0;

                    float t2 = t * t;
                    float t3 = t2 * t;
                    float omt = 1.f - t;
                    float u0 = omt * omt * omt;
                    float u1 = fmaf(3.f, t3, fmaf(-6.f, t2, 4.f));
                    float u3 = t3;
                    float u2 = ((6.f - u0) - u1) - u3;        // partition of unity

                    const float* cf = col + (d * 14 + jc) * 128;
                    float sa = u0 * cf[0];
                    sa = fmaf(u1, cf[128], sa);
                    sa = fmaf(u2, cf[256], sa);
                    sa = fmaf(u3, cf[384], sa);
                    acc = fmaf(sa, vm, acc);                  // uw already folded in

                    float sig = 1.f / (1.f + __expf(-x));
                    acc = fmaf(x * sig, rw[d], acc);
                }
                ob[(size_t)(c0 + cc) * HWn] = acc;
            }
        }
    }
}

// ---------------- launch ----------------
extern "C" void kernel_launch(void* const* d_in, const int* in_sizes, int n_in,
                              void* d_out, int out_size) {
    const float* x  = (const float*)d_in[0];   // windowed_x [2,31,7,192,192]
    const float* gw = (const float*)d_in[1];   // gen_w [70,31,3,3]
    const float* gb = (const float*)d_in[2];   // gen_b [70]
    float* out = (float*)d_out;                // [2,31,192,192]

    cudaFuncSetAttribute(conv_wmma_kernel, cudaFuncAttributeMaxDynamicSharedMemorySize, CONV_SMEM);
    cudaFuncSetAttribute(kan_kernel,       cudaFuncAttributeMaxDynamicSharedMemorySize, KAN_SMEM_BYTES);

    wprep_kernel<<<(9 * 32 * 80 + 255) / 256, 256>>>(gw);
    mean_kernel<<<(Bn * Cn * HWn / 4) / 256, 256>>>(x);
    conv_wmma_kernel<<<dim3(Hn / 3, Bn), 384, CONV_SMEM>>>(gb);
    kan_kernel<<<dim3(HWn / 128, Bn), 128, KAN_SMEM_BYTES>>>(x, out);
}

// round 13
// speedup vs baseline: 2.8480x; 1.1280x over previous
#include <cuda_runtime.h>
#include <cuda_fp16.h>
#include <cuda_bf16.h>
#include <mma.h>
#include <cstdint>

using namespace nvcuda;

#define Bn 2
#define Cn 31
#define Dn 7
#define Hn 192
#define Wn 192
#define HWn (Hn * Wn)          // 36864
#define KP 70                  // KAN_PARAMS
#define COEF_LEN 56
#define NB 8                   // N_BASIS

// ---------------- scratch (no allocations allowed) ----------------
__device__ float  g_ctx[Bn * Cn * HWn];   // [B, C, H, W]
__device__ float  g_wts[Bn * KP * HWn];   // [B, 70, H, W]
__device__ __half g_wB[9 * 32 * 80];      // [kk][ci(pad32)][co(pad80)] fp16

// ---------------- kernel 0: one-time weight conversion ----------------
__global__ void wprep_kernel(const float* __restrict__ gw) {
    int idx = blockIdx.x * 256 + threadIdx.x;       // 9*32*80 = 23040
    if (idx >= 9 * 32 * 80) return;
    int kk = idx / 2560;
    int r  = idx - kk * 2560;
    int ci = r / 80;
    int co = r - ci * 80;
    float v = 0.f;
    if (ci < Cn && co < KP) v = gw[((size_t)co * Cn + ci) * 9 + kk];
    g_wB[idx] = __float2half(v);
}

// ---------------- kernel 1: mean over D (float4) ----------------
__global__ void mean_kernel(const float* __restrict__ x) {
    int i = blockIdx.x * 256 + threadIdx.x;        // float4 index
    const int HW4 = HWn / 4;                       // 9216
    int hw4 = i % HW4;
    int bc  = i / HW4;
    const float4* p = (const float4*)(x + (size_t)bc * Dn * HWn) + hw4;
    float4 s = make_float4(0.f, 0.f, 0.f, 0.f);
#pragma unroll
    for (int d = 0; d < Dn; d++) {
        float4 v = p[(size_t)d * HW4];
        s.x += v.x; s.y += v.y; s.z += v.z; s.w += v.w;
    }
    const float inv7 = 1.0f / 7.0f;
    s.x *= inv7; s.y *= inv7; s.z *= inv7; s.w *= inv7;
    ((float4*)g_ctx)[i] = s;
}

// ---------------- kernel 2: conv as 9 shifted GEMMs, single-wave (round-12 best) ----------------
#define LDA_A 40
#define SA_HALVES (5 * 208 * LDA_A)            // 41,600 -> 83,200 B
#define SB_OFF (SA_HALVES * 2)                 // 83,200
#define SB_HALVES (9 * 32 * 80)                // 23,040 -> 46,080 B
#define CONV_SMEM (SB_OFF + SB_HALVES * 2)     // 129,280 B

__global__ void __launch_bounds__(384, 1)
conv_wmma_kernel(const float* __restrict__ gb) {
    extern __shared__ char sm[];
    __half* sA = (__half*)sm;
    __half* sB = (__half*)(sm + SB_OFF);
    float*  sC = (float*)sm;                      // overlays sA after mainloop

    int tid = threadIdx.x;
    int wid = tid >> 5, lane = tid & 31;
    int y0 = blockIdx.x * 3;                      // first of 3 image rows
    int b  = blockIdx.y;

    // ---- stage B: u32 copy ----
    {
        const uint32_t* src = (const uint32_t*)g_wB;
        uint32_t* dst = (uint32_t*)sB;
#pragma unroll
        for (int i = 0; i < SB_HALVES / 2; i += 384)
            dst[i + tid] = src[i + tid];
    }

    // ---- stage A: ctx rows y0-1..y0+3 (5 rows), rx 0..207 (gx = rx-1), 32 ci ----
    {
        const float* ctx = g_ctx + (size_t)b * Cn * HWn;
        int g = tid >> 5;                          // 0..11
#pragma unroll 1
        for (int s = 0; s < 14; s++) {
            int combo = s * 12 + g;                // 0..159 = (ry, ci)
            if (combo < 160) {
                int ry = combo >> 5;               // 0..4
                int ci = combo & 31;
                int gy = y0 - 1 + ry;
                bool rowok = (ci < Cn) && (gy >= 0) && (gy < Hn);
                const float* srow = ctx + (size_t)ci * HWn + (size_t)gy * Wn;
                __half* drow = sA + (size_t)(ry * 208) * LDA_A + ci;
#pragma unroll
                for (int rseg = 0; rseg < 7; rseg++) {
                    int rx = rseg * 32 + lane;
                    if (rx < 208) {
                        int gx = rx - 1;
                        float v = (rowok && gx >= 0 && gx < Wn) ? srow[gx] : 0.f;
                        drow[(size_t)rx * LDA_A] = __float2half(v);
                    }
                }
            }
        }
    }
    __syncthreads();

    // ---- mainloop: acc[3][5] ----
    wmma::fragment<wmma::accumulator, 16, 16, 16, float> acc[3][5];
#pragma unroll
    for (int mt = 0; mt < 3; mt++)
#pragma unroll
        for (int nt = 0; nt < 5; nt++) wmma::fill_fragment(acc[mt][nt], 0.f);

    int mbase = wid * 3;
#pragma unroll
    for (int kk = 0; kk < 9; kk++) {
        const int dy = kk / 3, dx = kk % 3;
#pragma unroll
        for (int ks = 0; ks < 2; ks++) {
            wmma::fragment<wmma::matrix_a, 16, 16, 16, __half, wmma::row_major> af[3];
#pragma unroll
            for (int mt = 0; mt < 3; mt++) {
                int m = mbase + mt;                 // 0..35
                int yr = m / 12;
                int xt = m - 12 * yr;
                int p0 = (yr + dy) * 208 + xt * 16 + dx;
                wmma::load_matrix_sync(af[mt], sA + (size_t)p0 * LDA_A + ks * 16, LDA_A);
            }
#pragma unroll
            for (int nt = 0; nt < 5; nt++) {
                wmma::fragment<wmma::matrix_b, 16, 16, 16, __half, wmma::row_major> bf;
                wmma::load_matrix_sync(bf, sB + kk * 2560 + ks * 16 * 80 + nt * 16, 80);
#pragma unroll
                for (int mt = 0; mt < 3; mt++)
                    wmma::mma_sync(acc[mt][nt], af[mt], bf, acc[mt][nt]);
            }
        }
    }

    __syncthreads();   // all warps done reading sA before sC overlays it

    // ---- epilogue ----
    float* sCw = sC + (size_t)wid * 16 * 84;
    float* outp = g_wts + (size_t)b * KP * HWn;
#pragma unroll
    for (int mt = 0; mt < 3; mt++) {
        int m = mbase + mt;
        int yr = m / 12;
        int xt = m - 12 * yr;
#pragma unroll
        for (int nt = 0; nt < 5; nt++)
            wmma::store_matrix_sync(sCw + nt * 16, acc[mt][nt], 84, wmma::mem_row_major);
        __syncwarp();
        int pix0 = (y0 + yr) * Wn + xt * 16;
        int px = lane & 15;
        int ch = lane >> 4;                        // 0/1
#pragma unroll 1
        for (int i = 0; i < 35; i++) {
            int co = i * 2 + ch;                   // 0..69
            outp[(size_t)co * HWn + pix0 + px] = sCw[(size_t)px * 84 + co] + __ldg(gb + co);
        }
        __syncwarp();
    }
}

// ---------------- kernel 3: kan — tanh silu, mask-free clamp, merged dot ----------------
// Table: 99 slots x 128 px transposed (conflict-free). Out-of-range j clamps to
// slot 11; slots d*14+{11,12,13,14} are all zero (14 = next d's pad 0; slot 98 extra zero).
#define KAN_SLOTS 99
#define KAN_SMEM_BYTES (KAN_SLOTS * 128 * 4)

__device__ __forceinline__ float tanh_approx(float v) {
    float r;
    asm("tanh.approx.f32 %0, %1;" : "=f"(r) : "f"(v));
    return r;
}

__global__ void __launch_bounds__(128, 4)
kan_kernel(const float* __restrict__ xin, float* __restrict__ out) {
    extern __shared__ float smem[];
    int tid = threadIdx.x;
    int b = blockIdx.y;
    int p = blockIdx.x * 128 + tid;

    float* col = smem + tid;                      // (slot s, px tid) at s*128 + tid
    const float* wbase = g_wts + (size_t)b * KP * HWn + p;

    float uw[Dn], rw[Dn];
#pragma unroll
    for (int d = 0; d < Dn; d++) {
        uw[d] = wbase[(size_t)(COEF_LEN + d) * HWn] * (1.0f / 6.0f);  // spline 1/6 folded
        rw[d] = wbase[(size_t)(COEF_LEN + Dn + d) * HWn];
    }

    // zero pads (slots 0-2, 11-13 per d; plus final slot 98)
#pragma unroll
    for (int d = 0; d < Dn; d++) {
        col[(d * 14 + 0) * 128]  = 0.f; col[(d * 14 + 1) * 128]  = 0.f; col[(d * 14 + 2) * 128]  = 0.f;
        col[(d * 14 + 11) * 128] = 0.f; col[(d * 14 + 12) * 128] = 0.f; col[(d * 14 + 13) * 128] = 0.f;
    }
    col[98 * 128] = 0.f;
    // coefficients premultiplied by uw[d]/6
#pragma unroll
    for (int k = 0; k < COEF_LEN; k++) {
        int d = k >> 3, g = k & 7;
        col[(d * 14 + 3 + g) * 128] = wbase[(size_t)k * HWn] * uw[d];
    }

    const float* xb = xin + (size_t)b * Cn * Dn * HWn + p;
    float* ob = out + (size_t)b * Cn * HWn + p;

#pragma unroll 1
    for (int c0 = 0; c0 < Cn; c0 += 4) {
        float xv[4][Dn];
#pragma unroll
        for (int cc = 0; cc < 4; cc++) {
            if (c0 + cc < Cn) {
#pragma unroll
                for (int d = 0; d < Dn; d++)
                    xv[cc][d] = xb[(size_t)((c0 + cc) * Dn + d) * HWn];
            }
        }
#pragma unroll
        for (int cc = 0; cc < 4; cc++) {
            if (c0 + cc < Cn) {
                float acc = 0.f;
#pragma unroll
                for (int d = 0; d < Dn; d++) {
                    float x = xv[cc][d];
                    float xs = fmaf(x, 2.5f, 5.5f);
                    float jf = floorf(xs);
                    int j = (int)jf;
                    float t = xs - jf;
                    int jc = ((unsigned)j <= 10u) ? j : 11;   // clamp -> all-zero slots

                    float t2 = t * t;
                    float omt = 1.f - t;
                    float u0 = omt * omt * omt;
                    float u3 = t2 * t;
                    float u1 = fmaf(t2, fmaf(3.f, t, -6.f), 4.f);
                    float u2 = ((6.f - u0) - u1) - u3;        // partition of unity

                    const float* cf = col + (d * 14 + jc) * 128;
                    acc = fmaf(u0, cf[0],   acc);
                    acc = fmaf(u1, cf[128], acc);
                    acc = fmaf(u2, cf[256], acc);
                    acc = fmaf(u3, cf[384], acc);

                    // silu(x) = h + h*tanh(h), h = x/2   (1 MUFU instead of 2)
                    float h = 0.5f * x;
                    float th = tanh_approx(h);
                    float sl = fmaf(h, th, h);
                    acc = fmaf(sl, rw[d], acc);
                }
                ob[(size_t)(c0 + cc) * HWn] = acc;
            }
        }
    }
}

// ---------------- launch ----------------
extern "C" void kernel_launch(void* const* d_in, const int* in_sizes, int n_in,
                              void* d_out, int out_size) {
    const float* x  = (const float*)d_in[0];   // windowed_x [2,31,7,192,192]
    const float* gw = (const float*)d_in[1];   // gen_w [70,31,3,3]
    const float* gb = (const float*)d_in[2];   // gen_b [70]
    float* out = (float*)d_out;                // [2,31,192,192]

    cudaFuncSetAttribute(conv_wmma_kernel, cudaFuncAttributeMaxDynamicSharedMemorySize, CONV_SMEM);
    cudaFuncSetAttribute(kan_kernel,       cudaFuncAttributeMaxDynamicSharedMemorySize, KAN_SMEM_BYTES);

    wprep_kernel<<<(9 * 32 * 80 + 255) / 256, 256>>>(gw);
    mean_kernel<<<(Bn * Cn * HWn / 4) / 256, 256>>>(x);
    conv_wmma_kernel<<<dim3(Hn / 3, Bn), 384, CONV_SMEM>>>(gb);
    kan_kernel<<<dim3(HWn / 128, Bn), 128, KAN_SMEM_BYTES>>>(x, out);
}

// round 14
// speedup vs baseline: 2.9322x; 1.0296x over previous
#include <cuda_runtime.h>
#include <cuda_fp16.h>
#include <cuda_bf16.h>
#include <mma.h>
#include <cstdint>

using namespace nvcuda;

#define Bn 2
#define Cn 31
#define Dn 7
#define Hn 192
#define Wn 192
#define HWn (Hn * Wn)          // 36864
#define KP 70                  // KAN_PARAMS
#define COEF_LEN 56
#define NB 8                   // N_BASIS

// ---------------- scratch (no allocations allowed) ----------------
__device__ float  g_ctx[Bn * Cn * HWn];   // [B, C, H, W]
__device__ float  g_wts[Bn * KP * HWn];   // [B, 70, H, W]
__device__ __half g_wB[9 * 32 * 80];      // [kk][ci(pad32)][co(pad80)] fp16

// ---------------- kernel 1: mean over D (float4) + fused weight prep ----------------
__global__ void mean_kernel(const float* __restrict__ x, const float* __restrict__ gw) {
    int i = blockIdx.x * 256 + threadIdx.x;        // float4 index
    const int HW4 = HWn / 4;                       // 9216
    int hw4 = i % HW4;
    int bc  = i / HW4;
    const float4* p = (const float4*)(x + (size_t)bc * Dn * HWn) + hw4;
    float4 s = make_float4(0.f, 0.f, 0.f, 0.f);
#pragma unroll
    for (int d = 0; d < Dn; d++) {
        float4 v = p[(size_t)d * HW4];
        s.x += v.x; s.y += v.y; s.z += v.z; s.w += v.w;
    }
    const float inv7 = 1.0f / 7.0f;
    s.x *= inv7; s.y *= inv7; s.z *= inv7; s.w *= inv7;
    ((float4*)g_ctx)[i] = s;

    // fused one-time weight conversion (first 90 blocks cover 9*32*80 = 23040)
    if (i < 9 * 32 * 80) {
        int kk = i / 2560;
        int r  = i - kk * 2560;
        int ci = r / 80;
        int co = r - ci * 80;
        float v = 0.f;
        if (ci < Cn && co < KP) v = gw[((size_t)co * Cn + ci) * 9 + kk];
        g_wB[i] = __float2half(v);
    }
}

// ---------------- kernel 2: conv as 9 shifted GEMMs, single-wave (round-12 best) ----------------
#define LDA_A 40
#define SA_HALVES (5 * 208 * LDA_A)            // 41,600 -> 83,200 B
#define SB_OFF (SA_HALVES * 2)                 // 83,200
#define SB_HALVES (9 * 32 * 80)                // 23,040 -> 46,080 B
#define CONV_SMEM (SB_OFF + SB_HALVES * 2)     // 129,280 B

__global__ void __launch_bounds__(384, 1)
conv_wmma_kernel(const float* __restrict__ gb) {
    extern __shared__ char sm[];
    __half* sA = (__half*)sm;
    __half* sB = (__half*)(sm + SB_OFF);
    float*  sC = (float*)sm;                      // overlays sA after mainloop

    int tid = threadIdx.x;
    int wid = tid >> 5, lane = tid & 31;
    int y0 = blockIdx.x * 3;                      // first of 3 image rows
    int b  = blockIdx.y;

    // ---- stage B: u32 copy ----
    {
        const uint32_t* src = (const uint32_t*)g_wB;
        uint32_t* dst = (uint32_t*)sB;
#pragma unroll
        for (int i = 0; i < SB_HALVES / 2; i += 384)
            dst[i + tid] = src[i + tid];
    }

    // ---- stage A: ctx rows y0-1..y0+3 (5 rows), rx 0..207 (gx = rx-1), 32 ci ----
    {
        const float* ctx = g_ctx + (size_t)b * Cn * HWn;
        int g = tid >> 5;                          // 0..11
#pragma unroll 1
        for (int s = 0; s < 14; s++) {
            int combo = s * 12 + g;                // 0..159 = (ry, ci)
            if (combo < 160) {
                int ry = combo >> 5;               // 0..4
                int ci = combo & 31;
                int gy = y0 - 1 + ry;
                bool rowok = (ci < Cn) && (gy >= 0) && (gy < Hn);
                const float* srow = ctx + (size_t)ci * HWn + (size_t)gy * Wn;
                __half* drow = sA + (size_t)(ry * 208) * LDA_A + ci;
#pragma unroll
                for (int rseg = 0; rseg < 7; rseg++) {
                    int rx = rseg * 32 + lane;
                    if (rx < 208) {
                        int gx = rx - 1;
                        float v = (rowok && gx >= 0 && gx < Wn) ? srow[gx] : 0.f;
                        drow[(size_t)rx * LDA_A] = __float2half(v);
                    }
                }
            }
        }
    }
    __syncthreads();

    // ---- mainloop: acc[3][5] ----
    wmma::fragment<wmma::accumulator, 16, 16, 16, float> acc[3][5];
#pragma unroll
    for (int mt = 0; mt < 3; mt++)
#pragma unroll
        for (int nt = 0; nt < 5; nt++) wmma::fill_fragment(acc[mt][nt], 0.f);

    int mbase = wid * 3;
#pragma unroll
    for (int kk = 0; kk < 9; kk++) {
        const int dy = kk / 3, dx = kk % 3;
#pragma unroll
        for (int ks = 0; ks < 2; ks++) {
            wmma::fragment<wmma::matrix_a, 16, 16, 16, __half, wmma::row_major> af[3];
#pragma unroll
            for (int mt = 0; mt < 3; mt++) {
                int m = mbase + mt;                 // 0..35
                int yr = m / 12;
                int xt = m - 12 * yr;
                int p0 = (yr + dy) * 208 + xt * 16 + dx;
                wmma::load_matrix_sync(af[mt], sA + (size_t)p0 * LDA_A + ks * 16, LDA_A);
            }
#pragma unroll
            for (int nt = 0; nt < 5; nt++) {
                wmma::fragment<wmma::matrix_b, 16, 16, 16, __half, wmma::row_major> bf;
                wmma::load_matrix_sync(bf, sB + kk * 2560 + ks * 16 * 80 + nt * 16, 80);
#pragma unroll
                for (int mt = 0; mt < 3; mt++)
                    wmma::mma_sync(acc[mt][nt], af[mt], bf, acc[mt][nt]);
            }
        }
    }

    __syncthreads();   // all warps done reading sA before sC overlays it

    // ---- epilogue ----
    float* sCw = sC + (size_t)wid * 16 * 84;
    float* outp = g_wts + (size_t)b * KP * HWn;
#pragma unroll
    for (int mt = 0; mt < 3; mt++) {
        int m = mbase + mt;
        int yr = m / 12;
        int xt = m - 12 * yr;
#pragma unroll
        for (int nt = 0; nt < 5; nt++)
            wmma::store_matrix_sync(sCw + nt * 16, acc[mt][nt], 84, wmma::mem_row_major);
        __syncwarp();
        int pix0 = (y0 + yr) * Wn + xt * 16;
        int px = lane & 15;
        int ch = lane >> 4;                        // 0/1
#pragma unroll 1
        for (int i = 0; i < 35; i++) {
            int co = i * 2 + ch;                   // 0..69
            outp[(size_t)co * HWn + pix0 + px] = sCw[(size_t)px * 84 + co] + __ldg(gb + co);
        }
        __syncwarp();
    }
}

// ---------------- kernel 3: kan — 3 independent accumulator chains ----------------
#define KAN_SLOTS 99
#define KAN_SMEM_BYTES (KAN_SLOTS * 128 * 4)

__device__ __forceinline__ float tanh_approx(float v) {
    float r;
    asm("tanh.approx.f32 %0, %1;" : "=f"(r) : "f"(v));
    return r;
}

__global__ void __launch_bounds__(128, 4)
kan_kernel(const float* __restrict__ xin, float* __restrict__ out) {
    extern __shared__ float smem[];
    int tid = threadIdx.x;
    int b = blockIdx.y;
    int p = blockIdx.x * 128 + tid;

    float* col = smem + tid;                      // (slot s, px tid) at s*128 + tid
    const float* wbase = g_wts + (size_t)b * KP * HWn + p;

    float uw[Dn], rw[Dn];
#pragma unroll
    for (int d = 0; d < Dn; d++) {
        uw[d] = wbase[(size_t)(COEF_LEN + d) * HWn] * (1.0f / 6.0f);  // spline 1/6 folded
        rw[d] = wbase[(size_t)(COEF_LEN + Dn + d) * HWn];
    }

    // zero pads (slots 0-2, 11-13 per d; plus final slot 98)
#pragma unroll
    for (int d = 0; d < Dn; d++) {
        col[(d * 14 + 0) * 128]  = 0.f; col[(d * 14 + 1) * 128]  = 0.f; col[(d * 14 + 2) * 128]  = 0.f;
        col[(d * 14 + 11) * 128] = 0.f; col[(d * 14 + 12) * 128] = 0.f; col[(d * 14 + 13) * 128] = 0.f;
    }
    col[98 * 128] = 0.f;
    // coefficients premultiplied by uw[d]/6
#pragma unroll
    for (int k = 0; k < COEF_LEN; k++) {
        int d = k >> 3, g = k & 7;
        col[(d * 14 + 3 + g) * 128] = wbase[(size_t)k * HWn] * uw[d];
    }

    const float* xb = xin + (size_t)b * Cn * Dn * HWn + p;
    float* ob = out + (size_t)b * Cn * HWn + p;

#pragma unroll 1
    for (int c0 = 0; c0 < Cn; c0 += 4) {
        float xv[4][Dn];
#pragma unroll
        for (int cc = 0; cc < 4; cc++) {
            if (c0 + cc < Cn) {
#pragma unroll
                for (int d = 0; d < Dn; d++)
                    xv[cc][d] = xb[(size_t)((c0 + cc) * Dn + d) * HWn];
            }
        }
#pragma unroll
        for (int cc = 0; cc < 4; cc++) {
            if (c0 + cc < Cn) {
                float accA = 0.f, accB = 0.f, accR = 0.f;   // 3 independent chains
#pragma unroll
                for (int d = 0; d < Dn; d++) {
                    float x = xv[cc][d];
                    float xs = fmaf(x, 2.5f, 5.5f);
                    float jf = floorf(xs);
                    int j = (int)jf;
                    float t = xs - jf;
                    int jc = ((unsigned)j <= 10u) ? j : 11;   // clamp -> all-zero slots

                    float t2 = t * t;
                    float omt = 1.f - t;
                    float u0 = omt * omt * omt;
                    float u3 = t2 * t;
                    float u1 = fmaf(t2, fmaf(3.f, t, -6.f), 4.f);
                    float u2 = ((6.f - u0) - u1) - u3;        // partition of unity

                    const float* cf = col + (d * 14 + jc) * 128;
                    accA = fmaf(u0, cf[0],   accA);
                    accB = fmaf(u1, cf[128], accB);
                    accA = fmaf(u2, cf[256], accA);
                    accB = fmaf(u3, cf[384], accB);

                    // silu(x) = h + h*tanh(h), h = x/2
                    float h = 0.5f * x;
                    float th = tanh_approx(h);
                    float sl = fmaf(h, th, h);
                    accR = fmaf(sl, rw[d], accR);
                }
                ob[(size_t)(c0 + cc) * HWn] = (accA + accB) + accR;
            }
        }
    }
}

// ---------------- launch ----------------
extern "C" void kernel_launch(void* const* d_in, const int* in_sizes, int n_in,
                              void* d_out, int out_size) {
    const float* x  = (const float*)d_in[0];   // windowed_x [2,31,7,192,192]
    const float* gw = (const float*)d_in[1];   // gen_w [70,31,3,3]
    const float* gb = (const float*)d_in[2];   // gen_b [70]
    float* out = (float*)d_out;                // [2,31,192,192]

    cudaFuncSetAttribute(conv_wmma_kernel, cudaFuncAttributeMaxDynamicSharedMemorySize, CONV_SMEM);
    cudaFuncSetAttribute(kan_kernel,       cudaFuncAttributeMaxDynamicSharedMemorySize, KAN_SMEM_BYTES);

    mean_kernel<<<(Bn * Cn * HWn / 4) / 256, 256>>>(x, gw);
    conv_wmma_kernel<<<dim3(Hn / 3, Bn), 384, CONV_SMEM>>>(gb);
    kan_kernel<<<dim3(HWn / 128, Bn), 128, KAN_SMEM_BYTES>>>(x, out);
}